// round 11
// baseline (speedup 1.0000x reference)
#include <cuda_runtime.h>
#include <math.h>
#include <stdint.h>

#define N_VEC  32768
#define DIM    256
#define KCODES 1024

#define OFF_QUANT  (N_VEC * DIM)
#define OFF_ENC    (2 * N_VEC * DIM)
#define OFF_QLOSS  (2 * N_VEC * DIM + N_VEC * KCODES)

#define THR 1.5e-4f

// mma tiling
#define BM 128
#define BN 128
#define BK 32
#define NCHUNKS (KCODES / BN)    // 8
#define KSITER  (DIM / BK)       // 8
#define NSLICES (NCHUNKS * KSITER) // 64
#define LDAS 260
#define LDBS 36
#define BSTGF (BN * LDBS)
#define LCAP 2048
#define GCAP (1 << 22)

// smem byte offsets
#define SO_A   0                 // 133120
#define SO_B   133120            // 4 * 18432 = 73728
#define SO_CN  206848
#define SO_FB  210944
#define SO_RC  211456
#define SO_LD  211968
#define SO_LP  220160
#define SO_CNT 228352
#define SM_TOTAL 228416

__device__ float g_wtf[KCODES * DIM];   // tf32-rounded, k-interleaved codebook
__device__ float g_codeNorm[KCODES];
__device__ float g_rowNorm[N_VEC];
__device__ unsigned long long g_key[N_VEC];
__device__ int   g_counts[KCODES];
__device__ float g_lossSum;
__device__ int   g_candCount;
__device__ unsigned int g_cand[GCAP];

// ---------------------------------------------------------------------------
__device__ __forceinline__ float tf32_rn(float x) {
    uint32_t u;
    asm("cvt.rna.tf32.f32 %0, %1;" : "=r"(u) : "f"(x));
    return __uint_as_float(u);
}
__device__ __forceinline__ uint32_t smem_u32(const void* p) {
    uint32_t a;
    asm("{ .reg .u64 t; cvta.to.shared.u64 t, %1; cvt.u32.u64 %0, t; }" : "=r"(a) : "l"(p));
    return a;
}
#define CP_ASYNC16(dst, src) \
    asm volatile("cp.async.cg.shared.global [%0], [%1], 16;" :: "r"(dst), "l"(src))
#define CP_COMMIT() asm volatile("cp.async.commit_group;" ::: "memory")
#define CP_WAIT(n)  asm volatile("cp.async.wait_group %0;" :: "n"(n) : "memory")

__device__ __forceinline__ void mma_tf32s(float* c, uint32_t a0, uint32_t a1,
                                          uint32_t a2, uint32_t a3,
                                          uint32_t b0, uint32_t b1) {
    asm volatile(
        "mma.sync.aligned.m16n8k8.row.col.f32.tf32.tf32.f32 "
        "{%0,%1,%2,%3}, {%4,%5,%6,%7}, {%8,%9}, {%0,%1,%2,%3};"
        : "+f"(c[0]), "+f"(c[1]), "+f"(c[2]), "+f"(c[3])
        : "r"(a0), "r"(a1), "r"(a2), "r"(a3), "r"(b0), "r"(b1));
}

// ---------------------------------------------------------------------------
// dummy: shifts the ncu -s 5 -c 1 profiling slot onto vq_mma.
__global__ void vq_dummy() {}

// vq_init: code norms (exact), tf32 + k-interleave pre-conversion of W, zeroing.
// Interleave within each 32-float k-slab: logical w = k8*8 + half*4 + tg
//   -> pos = tg*8 + half*4 + k8   (same mapping as the A tile staging)
__global__ void vq_init(const float* __restrict__ w)
{
    const int tid = threadIdx.x;
    const int warp = tid >> 5, lane = tid & 31;
    const int code = blockIdx.x * 8 + warp;
    const float* wr = w + (size_t)code * DIM;
    float s = 0.f;
#pragma unroll
    for (int i = 0; i < 8; i++) { float v = wr[lane + i * 32]; s = fmaf(v, v, s); }
#pragma unroll
    for (int o = 16; o > 0; o >>= 1) s += __shfl_xor_sync(0xffffffffu, s, o);
    if (lane == 0) g_codeNorm[code] = s;

    const float4* wsrc = (const float4*)w;
#pragma unroll
    for (int j = 0; j < 2; j++) {
        int i4 = blockIdx.x * 512 + tid + j * 256;
        float4 v = __ldg(wsrc + i4);
        int row = i4 >> 6, c4 = i4 & 63;
        float* base = g_wtf + (size_t)row * DIM
                    + (c4 >> 3) * 32 + (c4 & 1) * 4 + ((c4 & 7) >> 1);
        base[0]  = tf32_rn(v.x);
        base[8]  = tf32_rn(v.y);
        base[16] = tf32_rn(v.z);
        base[24] = tf32_rn(v.w);
    }

    if (blockIdx.x == 0) {
        for (int i = tid; i < KCODES; i += 256) g_counts[i] = 0;
        if (tid == 0) { g_lossSum = 0.f; g_candCount = 0; }
    }
}

__global__ void vq_rownorm(const float* __restrict__ inp)
{
    const int warp = threadIdx.x >> 5, lane = threadIdx.x & 31;
    const int row = blockIdx.x * 8 + warp;
    const float* xr = inp + (size_t)row * DIM;
    float s = 0.f;
#pragma unroll
    for (int i = 0; i < 8; i++) { float v = xr[lane + i * 32]; s = fmaf(v, v, s); }
#pragma unroll
    for (int o = 16; o > 0; o >>= 1) s += __shfl_xor_sync(0xffffffffu, s, o);
    if (lane == 0) { g_rowNorm[row] = s; g_key[row] = 0xFFFFFFFFFFFFFFFFull; }
}

// ---------------------------------------------------------------------------
extern __shared__ char dynsmem[];

// issue one B-slice (chunk t/8, k-slab t%8) into ring slot t&3 (bytes verbatim;
// g_wtf is already tf32 + interleaved)
__device__ __forceinline__ void issueB(uint32_t sbB, int t, int tid)
{
    const int c = t >> 3, s = t & 7, slot = t & 3;
    const uint32_t dbase = sbB + (uint32_t)slot * (uint32_t)(BSTGF * 4);
#pragma unroll
    for (int j = 0; j < 4; j++) {
        int gi = tid + j * 256;
        int col = gi >> 3, kq = gi & 7;
        uint32_t dst = dbase + (uint32_t)(col * LDBS + kq * 4) * 4u;
        const float* src = g_wtf + ((size_t)(c * BN + col) * DIM + s * BK + kq * 4);
        CP_ASYNC16(dst, src);
    }
    CP_COMMIT();
}

__global__ void __launch_bounds__(256, 1)
vq_mma(const float* __restrict__ X)
{
    float*    As  = (float*)(dynsmem + SO_A);
    float*    Bs  = (float*)(dynsmem + SO_B);
    float*    CNs = (float*)(dynsmem + SO_CN);
    float*    FBs = (float*)(dynsmem + SO_FB);
    int*      RC  = (int*)(dynsmem + SO_RC);
    float*    LD  = (float*)(dynsmem + SO_LD);
    unsigned* LP  = (unsigned*)(dynsmem + SO_LP);
    int*      s_cnt = (int*)(dynsmem + SO_CNT);

    const int tid = threadIdx.x;
    const int warp = tid >> 5, lane = tid & 31;
    const int wm = warp >> 1, wn = warp & 1;
    const int g = lane >> 2, tg = lane & 3;
    const int rowBase = blockIdx.x * BM;
    const uint32_t sbB = smem_u32(dynsmem + SO_B);

    if (tid == 0) *s_cnt = 0;
    if (tid < BM) RC[tid] = 0;

    issueB(sbB, 0, tid);
    issueB(sbB, 1, tid);
    issueB(sbB, 2, tid);

    // A tile: load, tf32-round, k-interleaved store
#pragma unroll
    for (int j = 0; j < 32; j++) {
        int l4 = tid + j * 256;
        int row = l4 >> 6, c4 = l4 & 63;
        float4 v = __ldg((const float4*)(X + (size_t)(rowBase + row) * DIM + c4 * 4));
        float* base = As + row * LDAS + (c4 >> 3) * 32 + (c4 & 1) * 4 + ((c4 & 7) >> 1);
        base[0]  = tf32_rn(v.x);
        base[8]  = tf32_rn(v.y);
        base[16] = tf32_rn(v.z);
        base[24] = tf32_rn(v.w);
    }
#pragma unroll
    for (int j = 0; j < 4; j++) CNs[tid + j * 256] = g_codeNorm[tid + j * 256];

    float xn[4], best[4];
#pragma unroll
    for (int s = 0; s < 4; s++) {
        int rl = wm * 32 + (s >> 1) * 16 + (s & 1) * 8 + g;
        xn[s] = g_rowNorm[rowBase + rl];
        best[s] = 3.4e38f;
    }
    __syncthreads();

    for (int c = 0; c < NCHUNKS; c++) {
        const int colBase = c * BN;
        float acc[2][8][4];
#pragma unroll
        for (int mi = 0; mi < 2; mi++)
#pragma unroll
            for (int ni = 0; ni < 8; ni++)
#pragma unroll
                for (int q = 0; q < 4; q++) acc[mi][ni][q] = 0.f;

        for (int s = 0; s < KSITER; s++) {
            const int t = c * KSITER + s;
            if (t < NSLICES - 3) CP_WAIT(2);
            else                 CP_WAIT(0);
            __syncthreads();
            const float* Bst = Bs + (t & 3) * BSTGF;

            // A fragments: 8 x LDS.128 (interleaved layout)
            float4 aL0[2], aL1[2], aH0[2], aH1[2];
#pragma unroll
            for (int mi = 0; mi < 2; mi++) {
                const float* ap = As + (wm * 32 + mi * 16 + g) * LDAS + s * 32 + tg * 8;
                aL0[mi] = *(const float4*)(ap);
                aL1[mi] = *(const float4*)(ap + 4);
                aH0[mi] = *(const float4*)(ap + 8 * LDAS);
                aH1[mi] = *(const float4*)(ap + 8 * LDAS + 4);
            }
            // B fragments: 2 x LDS.128 per ni (interleaved layout), then 4 k8 mmas
#pragma unroll
            for (int ni = 0; ni < 8; ni++) {
                const float* bp = Bst + (wn * 64 + ni * 8 + g) * LDBS + tg * 8;
                float4 b0v = *(const float4*)(bp);
                float4 b1v = *(const float4*)(bp + 4);
#pragma unroll
                for (int k8 = 0; k8 < 4; k8++) {
                    uint32_t b0 = __float_as_uint(((const float*)&b0v)[k8]);
                    uint32_t b1 = __float_as_uint(((const float*)&b1v)[k8]);
                    mma_tf32s(acc[0][ni],
                              __float_as_uint(((const float*)&aL0[0])[k8]),
                              __float_as_uint(((const float*)&aH0[0])[k8]),
                              __float_as_uint(((const float*)&aL1[0])[k8]),
                              __float_as_uint(((const float*)&aH1[0])[k8]),
                              b0, b1);
                    mma_tf32s(acc[1][ni],
                              __float_as_uint(((const float*)&aL0[1])[k8]),
                              __float_as_uint(((const float*)&aH0[1])[k8]),
                              __float_as_uint(((const float*)&aL1[1])[k8]),
                              __float_as_uint(((const float*)&aH1[1])[k8]),
                              b0, b1);
                }
            }
            if (t + 3 < NSLICES) issueB(sbB, t + 3, tid);
        }

        // epilogue: pass A (dists in-place + tighten), pass B (append)
        float cmin[4] = {3.4e38f, 3.4e38f, 3.4e38f, 3.4e38f};
#pragma unroll
        for (int mi = 0; mi < 2; mi++) {
            const int s0 = mi * 2, s1 = mi * 2 + 1;
#pragma unroll
            for (int ni = 0; ni < 8; ni++) {
                int col0 = colBase + wn * 64 + ni * 8 + tg * 2;
                float cn0 = CNs[col0], cn1 = CNs[col0 + 1];
                float d;
                d = __fadd_rn(__fadd_rn(xn[s0], cn0), -2.0f * acc[mi][ni][0]);
                acc[mi][ni][0] = d; cmin[s0] = fminf(cmin[s0], d);
                d = __fadd_rn(__fadd_rn(xn[s0], cn1), -2.0f * acc[mi][ni][1]);
                acc[mi][ni][1] = d; cmin[s0] = fminf(cmin[s0], d);
                d = __fadd_rn(__fadd_rn(xn[s1], cn0), -2.0f * acc[mi][ni][2]);
                acc[mi][ni][2] = d; cmin[s1] = fminf(cmin[s1], d);
                d = __fadd_rn(__fadd_rn(xn[s1], cn1), -2.0f * acc[mi][ni][3]);
                acc[mi][ni][3] = d; cmin[s1] = fminf(cmin[s1], d);
            }
        }
#pragma unroll
        for (int s = 0; s < 4; s++) {
            cmin[s] = fminf(cmin[s], __shfl_xor_sync(0xffffffffu, cmin[s], 1));
            cmin[s] = fminf(cmin[s], __shfl_xor_sync(0xffffffffu, cmin[s], 2));
            best[s] = fminf(best[s], cmin[s]);
        }
#pragma unroll
        for (int mi = 0; mi < 2; mi++) {
            const int rl0 = wm * 32 + mi * 16 + g;
            const int s0 = mi * 2, s1 = mi * 2 + 1;
#pragma unroll
            for (int ni = 0; ni < 8; ni++) {
                int col0 = colBase + wn * 64 + ni * 8 + tg * 2;
#pragma unroll
                for (int q = 0; q < 4; q++) {
                    float d = acc[mi][ni][q];
                    int s = (q >> 1) ? s1 : s0;
                    if (d <= best[s] + THR) {
                        int rl = rl0 + (q >> 1) * 8;
                        int col = col0 + (q & 1);
                        int i = atomicAdd(s_cnt, 1);
                        if (i < LCAP) {
                            LD[i] = d;
                            LP[i] = ((unsigned)rl << 10) | (unsigned)col;
                        } else {
                            int gi = atomicAdd(&g_candCount, 1);
                            if (gi < GCAP)
                                g_cand[gi] = ((unsigned)(rowBase + rl) << 10) | (unsigned)col;
                        }
                    }
                }
            }
        }
    }

    // per-row final approx best
    __syncthreads();
    if (wn == 0 && tg == 0) {
#pragma unroll
        for (int s = 0; s < 4; s++) {
            int rl = wm * 32 + (s >> 1) * 16 + (s & 1) * 8 + g;
            FBs[rl] = best[s];
        }
    }
    __syncthreads();
    if (wn == 1 && tg == 0) {
#pragma unroll
        for (int s = 0; s < 4; s++) {
            int rl = wm * 32 + (s >> 1) * 16 + (s & 1) * 8 + g;
            FBs[rl] = fminf(FBs[rl], best[s]);
        }
    }
    __syncthreads();

    const int n = min(*s_cnt, LCAP);
    const bool ovf = (*s_cnt > LCAP);
    for (int i = tid; i < n; i += 256) {
        unsigned p = LP[i];
        int rl = p >> 10;
        if (LD[i] <= FBs[rl] + THR) atomicAdd(&RC[rl], 1);
    }
    __syncthreads();
    for (int i = tid; i < n; i += 256) {
        unsigned p = LP[i];
        int rl = p >> 10;
        if (LD[i] <= FBs[rl] + THR) {
            unsigned col = p & 1023u;
            if (!ovf && RC[rl] == 1) {
                g_key[rowBase + rl] = (unsigned long long)col;
            } else {
                int gi = atomicAdd(&g_candCount, 1);
                if (gi < GCAP)
                    g_cand[gi] = ((unsigned)(rowBase + rl) << 10) | col;
            }
        }
    }
}

// ---------------------------------------------------------------------------
__global__ void __launch_bounds__(256)
vq_refine(const float* __restrict__ X, const float* __restrict__ W)
{
    __shared__ float buf[8][512];
    const int warp = threadIdx.x >> 5, lane = threadIdx.x & 31;
    const int wg = blockIdx.x * 8 + warp;
    const int nw = gridDim.x * 8;
    const int count = min(g_candCount, GCAP);
    for (int e = wg; e < count; e += nw) {
        unsigned ent = g_cand[e];
        int row = ent >> 10, col = ent & 1023;
#pragma unroll
        for (int j = 0; j < 8; j++) {
            buf[warp][lane + j * 32]       = __ldg(X + (size_t)row * DIM + lane + j * 32);
            buf[warp][256 + lane + j * 32] = __ldg(W + (size_t)col * DIM + lane + j * 32);
        }
        __syncwarp();
        if (lane == 0) {
            float acc = 0.f;
#pragma unroll 8
            for (int k = 0; k < DIM; k++)
                acc = fmaf(buf[warp][k], buf[warp][256 + k], acc);
            float t = __fadd_rn(g_rowNorm[row], g_codeNorm[col]);
            float d = __fadd_rn(t, -2.0f * acc);
            unsigned long long key =
                (((unsigned long long)__float_as_uint(d)) << 16) | (unsigned)col;
            atomicMin(&g_key[row], key);
        }
        __syncwarp();
    }
}

// ---------------------------------------------------------------------------
__global__ void vq_quant(const float* __restrict__ inp, const float* __restrict__ wt,
                         float* __restrict__ out)
{
    __shared__ float bsum[8];
    const int warp = threadIdx.x >> 5, lane = threadIdx.x & 31;
    const int row = blockIdx.x * 8 + warp;
    const int idx = (int)(g_key[row] & 0xFFFFull);

    const float4* x = (const float4*)(inp + (size_t)row * DIM);
    const float4* w = (const float4*)(wt + (size_t)idx * DIM);
    float4* oi = (float4*)(out + (size_t)row * DIM);
    float4* oq = (float4*)(out + OFF_QUANT + (size_t)row * DIM);
    float4* oe = (float4*)(out + OFF_ENC + (size_t)row * KCODES);

    float s = 0.f;
#pragma unroll
    for (int t = 0; t < 2; t++) {
        int p = lane + t * 32;
        float4 xv = __ldg(x + p);
        float4 wv = __ldg(w + p);
        oi[p] = xv;
        float4 qs;
        qs.x = __fadd_rn(xv.x, __fadd_rn(wv.x, -xv.x));
        qs.y = __fadd_rn(xv.y, __fadd_rn(wv.y, -xv.y));
        qs.z = __fadd_rn(xv.z, __fadd_rn(wv.z, -xv.z));
        qs.w = __fadd_rn(xv.w, __fadd_rn(wv.w, -xv.w));
        oq[p] = qs;
        float dx = wv.x - xv.x, dy = wv.y - xv.y;
        float dz = wv.z - xv.z, dw = wv.w - xv.w;
        s += dx * dx + dy * dy + dz * dz + dw * dw;
    }
#pragma unroll
    for (int t = 0; t < 8; t++) {
        int p = lane + t * 32;
        int base = p * 4;
        float4 v = make_float4(0.f, 0.f, 0.f, 0.f);
        int d = idx - base;
        if (d >= 0 && d < 4) {
            if (d == 0) v.x = 1.f; else if (d == 1) v.y = 1.f;
            else if (d == 2) v.z = 1.f; else v.w = 1.f;
        }
        oe[p] = v;
    }
#pragma unroll
    for (int o = 16; o > 0; o >>= 1) s += __shfl_xor_sync(0xffffffffu, s, o);
    if (lane == 0) { bsum[warp] = s; atomicAdd(&g_counts[idx], 1); }
    __syncthreads();
    if (threadIdx.x == 0) {
        float t = bsum[0] + bsum[1] + bsum[2] + bsum[3]
                + bsum[4] + bsum[5] + bsum[6] + bsum[7];
        atomicAdd(&g_lossSum, t);
    }
}

__global__ void vq_final(float* __restrict__ out)
{
    __shared__ float red[1024];
    int t = threadIdx.x;
    float p = (float)g_counts[t] * (1.0f / (float)N_VEC);
    red[t] = p * logf(p + 1e-10f);
    __syncthreads();
    for (int o = 512; o > 0; o >>= 1) {
        if (t < o) red[t] += red[t + o];
        __syncthreads();
    }
    if (t == 0) {
        float loss = g_lossSum * (1.0f / (float)(N_VEC * DIM));
        out[OFF_QLOSS]     = loss;
        out[OFF_QLOSS + 1] = loss;
        out[OFF_QLOSS + 2] = expf(-red[0]);
    }
}

// ---------------------------------------------------------------------------
extern "C" void kernel_launch(void* const* d_in, const int* in_sizes, int n_in,
                              void* d_out, int out_size)
{
    const float* inp = (const float*)d_in[0];
    const float* wt  = (const float*)d_in[1];
    if (n_in >= 2 && in_sizes[0] == KCODES * DIM && in_sizes[1] == N_VEC * DIM) {
        const float* tmp = inp; inp = wt; wt = tmp;
    }
    float* out = (float*)d_out;

    static bool attrDone = false;
    if (!attrDone) {
        (void)cudaFuncSetAttribute(vq_mma, cudaFuncAttributeMaxDynamicSharedMemorySize,
                                   SM_TOTAL);
        attrDone = true;
    }

    vq_dummy<<<1, 32>>>();                       // shifts ncu slot onto vq_mma
    vq_init<<<KCODES / 8, 256>>>(wt);
    vq_rownorm<<<N_VEC / 8, 256>>>(inp);
    vq_mma<<<N_VEC / BM, 256, SM_TOTAL>>>(inp);
    vq_refine<<<148, 256>>>(inp, wt);
    vq_quant<<<N_VEC / 8, 256>>>(inp, wt, out);
    vq_final<<<1, 1024>>>(out);
}

// round 12
// speedup vs baseline: 1.1506x; 1.1506x over previous
#include <cuda_runtime.h>
#include <math.h>
#include <stdint.h>

#define N_VEC  32768
#define DIM    256
#define KCODES 1024

#define OFF_QUANT  (N_VEC * DIM)
#define OFF_ENC    (2 * N_VEC * DIM)
#define OFF_QLOSS  (2 * N_VEC * DIM + N_VEC * KCODES)

#define THR 1.5e-4f

#define NT 512                   // threads per CTA (16 warps, 4x4)
#define BM 128
#define BN 128
#define BK 32
#define NCHUNKS (KCODES / BN)    // 8
#define KSITER  (DIM / BK)       // 8
#define NSLICES (NCHUNKS * KSITER) // 64
#define LDAS 260
#define LDBS 36
#define BSTGF (BN * LDBS)
#define LCAP 2048
#define GCAP (1 << 22)

// smem byte offsets
#define SO_A   0                 // 133120
#define SO_B   133120            // 4 * 18432 = 73728
#define SO_CN  206848
#define SO_FB  210944
#define SO_RC  211456
#define SO_LD  211968
#define SO_LP  220160
#define SO_CNT 228352
#define SM_TOTAL 228416

__device__ float g_wtf[KCODES * DIM];   // tf32-rounded codebook (plain layout)
__device__ float g_codeNorm[KCODES];
__device__ float g_rowNorm[N_VEC];
__device__ unsigned long long g_key[N_VEC];
__device__ int   g_counts[KCODES];
__device__ float g_lossSum;
__device__ int   g_candCount;
__device__ unsigned int g_cand[GCAP];

// ---------------------------------------------------------------------------
__device__ __forceinline__ float tf32_rn(float x) {
    uint32_t u;
    asm("cvt.rna.tf32.f32 %0, %1;" : "=r"(u) : "f"(x));
    return __uint_as_float(u);
}
__device__ __forceinline__ uint32_t smem_u32(const void* p) {
    uint32_t a;
    asm("{ .reg .u64 t; cvta.to.shared.u64 t, %1; cvt.u32.u64 %0, t; }" : "=r"(a) : "l"(p));
    return a;
}
#define CP_ASYNC16(dst, src) \
    asm volatile("cp.async.cg.shared.global [%0], [%1], 16;" :: "r"(dst), "l"(src))
#define CP_COMMIT() asm volatile("cp.async.commit_group;" ::: "memory")
#define CP_WAIT(n)  asm volatile("cp.async.wait_group %0;" :: "n"(n) : "memory")

__device__ __forceinline__ void mma_tf32(float* c, const uint32_t* a,
                                         uint32_t b0, uint32_t b1) {
    asm volatile(
        "mma.sync.aligned.m16n8k8.row.col.f32.tf32.tf32.f32 "
        "{%0,%1,%2,%3}, {%4,%5,%6,%7}, {%8,%9}, {%0,%1,%2,%3};"
        : "+f"(c[0]), "+f"(c[1]), "+f"(c[2]), "+f"(c[3])
        : "r"(a[0]), "r"(a[1]), "r"(a[2]), "r"(a[3]), "r"(b0), "r"(b1));
}

// ---------------------------------------------------------------------------
__global__ void vq_dummy() {}   // shifts the ncu -s 5 -c 1 slot onto vq_mma

// vq_init: code norms (exact), plain tf32 pre-conversion of W, zeroing.
__global__ void vq_init(const float* __restrict__ w)
{
    const int tid = threadIdx.x;
    const int warp = tid >> 5, lane = tid & 31;
    const int code = blockIdx.x * 8 + warp;
    const float* wr = w + (size_t)code * DIM;
    float s = 0.f;
#pragma unroll
    for (int i = 0; i < 8; i++) { float v = wr[lane + i * 32]; s = fmaf(v, v, s); }
#pragma unroll
    for (int o = 16; o > 0; o >>= 1) s += __shfl_xor_sync(0xffffffffu, s, o);
    if (lane == 0) g_codeNorm[code] = s;

    const float4* wsrc = (const float4*)w;
    float4* wdst = (float4*)g_wtf;
#pragma unroll
    for (int j = 0; j < 2; j++) {
        int i4 = blockIdx.x * 512 + tid + j * 256;
        float4 v = __ldg(wsrc + i4);
        float4 t;
        t.x = tf32_rn(v.x); t.y = tf32_rn(v.y);
        t.z = tf32_rn(v.z); t.w = tf32_rn(v.w);
        wdst[i4] = t;
    }

    if (blockIdx.x == 0) {
        for (int i = tid; i < KCODES; i += 256) g_counts[i] = 0;
        if (tid == 0) { g_lossSum = 0.f; g_candCount = 0; }
    }
}

__global__ void vq_rownorm(const float* __restrict__ inp)
{
    const int warp = threadIdx.x >> 5, lane = threadIdx.x & 31;
    const int row = blockIdx.x * 8 + warp;
    const float* xr = inp + (size_t)row * DIM;
    float s = 0.f;
#pragma unroll
    for (int i = 0; i < 8; i++) { float v = xr[lane + i * 32]; s = fmaf(v, v, s); }
#pragma unroll
    for (int o = 16; o > 0; o >>= 1) s += __shfl_xor_sync(0xffffffffu, s, o);
    if (lane == 0) { g_rowNorm[row] = s; g_key[row] = 0xFFFFFFFFFFFFFFFFull; }
}

// ---------------------------------------------------------------------------
extern __shared__ char dynsmem[];

// issue one B-slice (chunk t/8, k-slab t%8) into ring slot t&3
__device__ __forceinline__ void issueB(uint32_t sbB, int t, int tid)
{
    const int c = t >> 3, s = t & 7, slot = t & 3;
    const uint32_t dbase = sbB + (uint32_t)slot * (uint32_t)(BSTGF * 4);
#pragma unroll
    for (int j = 0; j < 2; j++) {
        int gi = tid + j * NT;
        int col = gi >> 3, kq = gi & 7;
        uint32_t dst = dbase + (uint32_t)(col * LDBS + kq * 4) * 4u;
        const float* src = g_wtf + ((size_t)(c * BN + col) * DIM + s * BK + kq * 4);
        CP_ASYNC16(dst, src);
    }
    CP_COMMIT();
}

__global__ void __launch_bounds__(NT, 1)
vq_mma(const float* __restrict__ X)
{
    float*    As  = (float*)(dynsmem + SO_A);
    float*    Bs  = (float*)(dynsmem + SO_B);
    float*    CNs = (float*)(dynsmem + SO_CN);
    float*    FBs = (float*)(dynsmem + SO_FB);
    int*      RC  = (int*)(dynsmem + SO_RC);
    float*    LD  = (float*)(dynsmem + SO_LD);
    unsigned* LP  = (unsigned*)(dynsmem + SO_LP);
    int*      s_cnt = (int*)(dynsmem + SO_CNT);

    const int tid = threadIdx.x;
    const int warp = tid >> 5, lane = tid & 31;
    const int wm = warp >> 2, wn = warp & 3;      // 4x4 warp grid
    const int g = lane >> 2, tg = lane & 3;
    const int rowBase = blockIdx.x * BM;
    const uint32_t sbB = smem_u32(dynsmem + SO_B);

    if (tid == 0) *s_cnt = 0;
    if (tid < BM) RC[tid] = 0;

    issueB(sbB, 0, tid);
    issueB(sbB, 1, tid);
    issueB(sbB, 2, tid);

    // A tile: load, tf32-round, k-interleaved store (validated layout)
#pragma unroll
    for (int j = 0; j < 16; j++) {
        int l4 = tid + j * NT;
        int row = l4 >> 6, c4 = l4 & 63;
        float4 v = __ldg((const float4*)(X + (size_t)(rowBase + row) * DIM + c4 * 4));
        float* base = As + row * LDAS + (c4 >> 3) * 32 + (c4 & 1) * 4 + ((c4 & 7) >> 1);
        base[0]  = tf32_rn(v.x);
        base[8]  = tf32_rn(v.y);
        base[16] = tf32_rn(v.z);
        base[24] = tf32_rn(v.w);
    }
#pragma unroll
    for (int j = 0; j < 2; j++) CNs[tid + j * NT] = g_codeNorm[tid + j * NT];

    float xn[4], best[4];
#pragma unroll
    for (int s = 0; s < 4; s++) {
        int rl = wm * 32 + (s >> 1) * 16 + (s & 1) * 8 + g;
        xn[s] = g_rowNorm[rowBase + rl];
        best[s] = 3.4e38f;
    }
    __syncthreads();

    for (int c = 0; c < NCHUNKS; c++) {
        const int colBase = c * BN;
        float acc[2][4][4];
#pragma unroll
        for (int mi = 0; mi < 2; mi++)
#pragma unroll
            for (int ni = 0; ni < 4; ni++)
#pragma unroll
                for (int q = 0; q < 4; q++) acc[mi][ni][q] = 0.f;

        for (int s = 0; s < KSITER; s++) {
            const int t = c * KSITER + s;
            if (t < NSLICES - 3) CP_WAIT(2);
            else                 CP_WAIT(0);
            __syncthreads();
            const float* Bst = Bs + (t & 3) * BSTGF;

            // A fragments: 8 x LDS.128 (interleaved layout, validated)
            float4 aL0[2], aL1[2], aH0[2], aH1[2];
#pragma unroll
            for (int mi = 0; mi < 2; mi++) {
                const float* ap = As + (wm * 32 + mi * 16 + g) * LDAS + s * 32 + tg * 8;
                aL0[mi] = *(const float4*)(ap);
                aL1[mi] = *(const float4*)(ap + 4);
                aH0[mi] = *(const float4*)(ap + 8 * LDAS);
                aH1[mi] = *(const float4*)(ap + 8 * LDAS + 4);
            }
            // k8-outer, scalar conflict-free B reads (validated R10 pattern)
#pragma unroll
            for (int k8 = 0; k8 < 4; k8++) {
                const int kb = k8 * 8 + tg;
                uint32_t aF[2][4];
#pragma unroll
                for (int mi = 0; mi < 2; mi++) {
                    aF[mi][0] = __float_as_uint(((const float*)&aL0[mi])[k8]);
                    aF[mi][1] = __float_as_uint(((const float*)&aH0[mi])[k8]);
                    aF[mi][2] = __float_as_uint(((const float*)&aL1[mi])[k8]);
                    aF[mi][3] = __float_as_uint(((const float*)&aH1[mi])[k8]);
                }
#pragma unroll
                for (int ni = 0; ni < 4; ni++) {
                    const float* bp = Bst + (wn * 32 + ni * 8 + g) * LDBS;
                    uint32_t b0 = __float_as_uint(bp[kb]);
                    uint32_t b1 = __float_as_uint(bp[kb + 4]);
                    mma_tf32(acc[0][ni], aF[0], b0, b1);
                    mma_tf32(acc[1][ni], aF[1], b0, b1);
                }
            }
            if (t + 3 < NSLICES) issueB(sbB, t + 3, tid);
        }

        // epilogue: pass A (dists in-place + tighten), pass B (append)
        float cmin[4] = {3.4e38f, 3.4e38f, 3.4e38f, 3.4e38f};
#pragma unroll
        for (int mi = 0; mi < 2; mi++) {
            const int s0 = mi * 2, s1 = mi * 2 + 1;
#pragma unroll
            for (int ni = 0; ni < 4; ni++) {
                int col0 = colBase + wn * 32 + ni * 8 + tg * 2;
                float cn0 = CNs[col0], cn1 = CNs[col0 + 1];
                float d;
                d = __fadd_rn(__fadd_rn(xn[s0], cn0), -2.0f * acc[mi][ni][0]);
                acc[mi][ni][0] = d; cmin[s0] = fminf(cmin[s0], d);
                d = __fadd_rn(__fadd_rn(xn[s0], cn1), -2.0f * acc[mi][ni][1]);
                acc[mi][ni][1] = d; cmin[s0] = fminf(cmin[s0], d);
                d = __fadd_rn(__fadd_rn(xn[s1], cn0), -2.0f * acc[mi][ni][2]);
                acc[mi][ni][2] = d; cmin[s1] = fminf(cmin[s1], d);
                d = __fadd_rn(__fadd_rn(xn[s1], cn1), -2.0f * acc[mi][ni][3]);
                acc[mi][ni][3] = d; cmin[s1] = fminf(cmin[s1], d);
            }
        }
#pragma unroll
        for (int s = 0; s < 4; s++) {
            cmin[s] = fminf(cmin[s], __shfl_xor_sync(0xffffffffu, cmin[s], 1));
            cmin[s] = fminf(cmin[s], __shfl_xor_sync(0xffffffffu, cmin[s], 2));
            best[s] = fminf(best[s], cmin[s]);
        }
#pragma unroll
        for (int mi = 0; mi < 2; mi++) {
            const int rl0 = wm * 32 + mi * 16 + g;
            const int s0 = mi * 2, s1 = mi * 2 + 1;
#pragma unroll
            for (int ni = 0; ni < 4; ni++) {
                int col0 = colBase + wn * 32 + ni * 8 + tg * 2;
#pragma unroll
                for (int q = 0; q < 4; q++) {
                    float d = acc[mi][ni][q];
                    int s = (q >> 1) ? s1 : s0;
                    if (d <= best[s] + THR) {
                        int rl = rl0 + (q >> 1) * 8;
                        int col = col0 + (q & 1);
                        int i = atomicAdd(s_cnt, 1);
                        if (i < LCAP) {
                            LD[i] = d;
                            LP[i] = ((unsigned)rl << 10) | (unsigned)col;
                        } else {
                            int gi = atomicAdd(&g_candCount, 1);
                            if (gi < GCAP)
                                g_cand[gi] = ((unsigned)(rowBase + rl) << 10) | (unsigned)col;
                        }
                    }
                }
            }
        }
    }

    // per-row final approx best: 4 sequential merge rounds over wn
    __syncthreads();
    for (int r = 0; r < 4; r++) {
        if (wn == r && tg == 0) {
#pragma unroll
            for (int s = 0; s < 4; s++) {
                int rl = wm * 32 + (s >> 1) * 16 + (s & 1) * 8 + g;
                FBs[rl] = (r == 0) ? best[s] : fminf(FBs[rl], best[s]);
            }
        }
        __syncthreads();
    }

    const int n = min(*s_cnt, LCAP);
    const bool ovf = (*s_cnt > LCAP);
    for (int i = tid; i < n; i += NT) {
        unsigned p = LP[i];
        int rl = p >> 10;
        if (LD[i] <= FBs[rl] + THR) atomicAdd(&RC[rl], 1);
    }
    __syncthreads();
    for (int i = tid; i < n; i += NT) {
        unsigned p = LP[i];
        int rl = p >> 10;
        if (LD[i] <= FBs[rl] + THR) {
            unsigned col = p & 1023u;
            if (!ovf && RC[rl] == 1) {
                g_key[rowBase + rl] = (unsigned long long)col;
            } else {
                int gi = atomicAdd(&g_candCount, 1);
                if (gi < GCAP)
                    g_cand[gi] = ((unsigned)(rowBase + rl) << 10) | col;
            }
        }
    }
}

// ---------------------------------------------------------------------------
__global__ void __launch_bounds__(256)
vq_refine(const float* __restrict__ X, const float* __restrict__ W)
{
    __shared__ float buf[8][512];
    const int warp = threadIdx.x >> 5, lane = threadIdx.x & 31;
    const int wg = blockIdx.x * 8 + warp;
    const int nw = gridDim.x * 8;
    const int count = min(g_candCount, GCAP);
    for (int e = wg; e < count; e += nw) {
        unsigned ent = g_cand[e];
        int row = ent >> 10, col = ent & 1023;
#pragma unroll
        for (int j = 0; j < 8; j++) {
            buf[warp][lane + j * 32]       = __ldg(X + (size_t)row * DIM + lane + j * 32);
            buf[warp][256 + lane + j * 32] = __ldg(W + (size_t)col * DIM + lane + j * 32);
        }
        __syncwarp();
        if (lane == 0) {
            float acc = 0.f;
#pragma unroll 8
            for (int k = 0; k < DIM; k++)
                acc = fmaf(buf[warp][k], buf[warp][256 + k], acc);
            float t = __fadd_rn(g_rowNorm[row], g_codeNorm[col]);
            float d = __fadd_rn(t, -2.0f * acc);
            unsigned long long key =
                (((unsigned long long)__float_as_uint(d)) << 16) | (unsigned)col;
            atomicMin(&g_key[row], key);
        }
        __syncwarp();
    }
}

// ---------------------------------------------------------------------------
__global__ void vq_quant(const float* __restrict__ inp, const float* __restrict__ wt,
                         float* __restrict__ out)
{
    __shared__ float bsum[8];
    const int warp = threadIdx.x >> 5, lane = threadIdx.x & 31;
    const int row = blockIdx.x * 8 + warp;
    const int idx = (int)(g_key[row] & 0xFFFFull);

    const float4* x = (const float4*)(inp + (size_t)row * DIM);
    const float4* w = (const float4*)(wt + (size_t)idx * DIM);
    float4* oi = (float4*)(out + (size_t)row * DIM);
    float4* oq = (float4*)(out + OFF_QUANT + (size_t)row * DIM);
    float4* oe = (float4*)(out + OFF_ENC + (size_t)row * KCODES);

    float s = 0.f;
#pragma unroll
    for (int t = 0; t < 2; t++) {
        int p = lane + t * 32;
        float4 xv = __ldg(x + p);
        float4 wv = __ldg(w + p);
        oi[p] = xv;
        float4 qs;
        qs.x = __fadd_rn(xv.x, __fadd_rn(wv.x, -xv.x));
        qs.y = __fadd_rn(xv.y, __fadd_rn(wv.y, -xv.y));
        qs.z = __fadd_rn(xv.z, __fadd_rn(wv.z, -xv.z));
        qs.w = __fadd_rn(xv.w, __fadd_rn(wv.w, -xv.w));
        oq[p] = qs;
        float dx = wv.x - xv.x, dy = wv.y - xv.y;
        float dz = wv.z - xv.z, dw = wv.w - xv.w;
        s += dx * dx + dy * dy + dz * dz + dw * dw;
    }
#pragma unroll
    for (int t = 0; t < 8; t++) {
        int p = lane + t * 32;
        int base = p * 4;
        float4 v = make_float4(0.f, 0.f, 0.f, 0.f);
        int d = idx - base;
        if (d >= 0 && d < 4) {
            if (d == 0) v.x = 1.f; else if (d == 1) v.y = 1.f;
            else if (d == 2) v.z = 1.f; else v.w = 1.f;
        }
        oe[p] = v;
    }
#pragma unroll
    for (int o = 16; o > 0; o >>= 1) s += __shfl_xor_sync(0xffffffffu, s, o);
    if (lane == 0) { bsum[warp] = s; atomicAdd(&g_counts[idx], 1); }
    __syncthreads();
    if (threadIdx.x == 0) {
        float t = bsum[0] + bsum[1] + bsum[2] + bsum[3]
                + bsum[4] + bsum[5] + bsum[6] + bsum[7];
        atomicAdd(&g_lossSum, t);
    }
}

__global__ void vq_final(float* __restrict__ out)
{
    __shared__ float red[1024];
    int t = threadIdx.x;
    float p = (float)g_counts[t] * (1.0f / (float)N_VEC);
    red[t] = p * logf(p + 1e-10f);
    __syncthreads();
    for (int o = 512; o > 0; o >>= 1) {
        if (t < o) red[t] += red[t + o];
        __syncthreads();
    }
    if (t == 0) {
        float loss = g_lossSum * (1.0f / (float)(N_VEC * DIM));
        out[OFF_QLOSS]     = loss;
        out[OFF_QLOSS + 1] = loss;
        out[OFF_QLOSS + 2] = expf(-red[0]);
    }
}

// ---------------------------------------------------------------------------
extern "C" void kernel_launch(void* const* d_in, const int* in_sizes, int n_in,
                              void* d_out, int out_size)
{
    const float* inp = (const float*)d_in[0];
    const float* wt  = (const float*)d_in[1];
    if (n_in >= 2 && in_sizes[0] == KCODES * DIM && in_sizes[1] == N_VEC * DIM) {
        const float* tmp = inp; inp = wt; wt = tmp;
    }
    float* out = (float*)d_out;

    static bool attrDone = false;
    if (!attrDone) {
        (void)cudaFuncSetAttribute(vq_mma, cudaFuncAttributeMaxDynamicSharedMemorySize,
                                   SM_TOTAL);
        attrDone = true;
    }

    vq_dummy<<<1, 32>>>();                        // keeps ncu slot on vq_mma
    vq_init<<<KCODES / 8, 256>>>(wt);
    vq_rownorm<<<N_VEC / 8, 256>>>(inp);
    vq_mma<<<N_VEC / BM, NT, SM_TOTAL>>>(inp);
    vq_refine<<<148, 256>>>(inp, wt);
    vq_quant<<<N_VEC / 8, 256>>>(inp, wt, out);
    vq_final<<<1, 1024>>>(out);
}

// round 15
// speedup vs baseline: 1.3452x; 1.1691x over previous
#include <cuda_runtime.h>
#include <math.h>
#include <stdint.h>

#define N_VEC  32768
#define DIM    256
#define KCODES 1024

#define OFF_QUANT  (N_VEC * DIM)
#define OFF_ENC    (2 * N_VEC * DIM)
#define OFF_QLOSS  (2 * N_VEC * DIM + N_VEC * KCODES)

#define THR 1.5e-4f

#define NT 512                   // 16 warps: 4 (M) x 4 (N)
#define BM 128
#define BG 256                   // col-group width
#define NGROUPS (KCODES / BG)    // 4
#define KSITER  (DIM / 32)       // 8
#define NITERS  (NGROUPS * KSITER) // 32
#define LDAS 260                 // A row stride (floats); scalar reads conflict-free
#define LDBS 36                  // B col stride (floats); scalar reads conflict-free
#define BSTGF (128 * LDBS)       // one half-slice: 128 cols x 32 k
#define LCAP 2048
#define GCAP (1 << 22)

// smem byte offsets
#define SO_A   0                 // 128*260*4 = 133120
#define SO_B   133120            // 4 * 18432 = 73728
#define SO_CN  206848            // 4096
#define SO_FB  210944            // 512
#define SO_RC  211456            // 512
#define SO_LD  211968            // 8192
#define SO_LP  220160            // 8192
#define SO_CNT 228352            // 64
#define SM_TOTAL 228416

__device__ float g_wtf[KCODES * DIM];   // tf32-rounded codebook (plain layout)
__device__ float g_codeNorm[KCODES];
__device__ float g_rowNorm[N_VEC];
__device__ unsigned long long g_key[N_VEC];
__device__ int   g_counts[KCODES];
__device__ float g_lossSum;
__device__ int   g_candCount;
__device__ unsigned int g_cand[GCAP];

// ---------------------------------------------------------------------------
__device__ __forceinline__ float tf32_rn(float x) {
    uint32_t u;
    asm("cvt.rna.tf32.f32 %0, %1;" : "=r"(u) : "f"(x));
    return __uint_as_float(u);
}
__device__ __forceinline__ uint32_t smem_u32(const void* p) {
    uint32_t a;
    asm("{ .reg .u64 t; cvta.to.shared.u64 t, %1; cvt.u32.u64 %0, t; }" : "=r"(a) : "l"(p));
    return a;
}
#define CP_ASYNC16(dst, src) \
    asm volatile("cp.async.cg.shared.global [%0], [%1], 16;" :: "r"(dst), "l"(src))
#define CP_COMMIT() asm volatile("cp.async.commit_group;" ::: "memory")
#define CP_WAIT(n)  asm volatile("cp.async.wait_group %0;" :: "n"(n) : "memory")

__device__ __forceinline__ void mma_tf32(float* c, const uint32_t* a,
                                         uint32_t b0, uint32_t b1) {
    asm volatile(
        "mma.sync.aligned.m16n8k8.row.col.f32.tf32.tf32.f32 "
        "{%0,%1,%2,%3}, {%4,%5,%6,%7}, {%8,%9}, {%0,%1,%2,%3};"
        : "+f"(c[0]), "+f"(c[1]), "+f"(c[2]), "+f"(c[3])
        : "r"(a[0]), "r"(a[1]), "r"(a[2]), "r"(a[3]), "r"(b0), "r"(b1));
}

// ---------------------------------------------------------------------------
__global__ void vq_dummy() {}   // keeps the ncu -s 5 -c 1 slot on vq_mma

__global__ void vq_init(const float* __restrict__ w)
{
    const int tid = threadIdx.x;
    const int warp = tid >> 5, lane = tid & 31;
    const int code = blockIdx.x * 8 + warp;
    const float* wr = w + (size_t)code * DIM;
    float s = 0.f;
#pragma unroll
    for (int i = 0; i < 8; i++) { float v = wr[lane + i * 32]; s = fmaf(v, v, s); }
#pragma unroll
    for (int o = 16; o > 0; o >>= 1) s += __shfl_xor_sync(0xffffffffu, s, o);
    if (lane == 0) g_codeNorm[code] = s;

    const float4* wsrc = (const float4*)w;
    float4* wdst = (float4*)g_wtf;
#pragma unroll
    for (int j = 0; j < 2; j++) {
        int i4 = blockIdx.x * 512 + tid + j * 256;
        float4 v = __ldg(wsrc + i4);
        float4 t;
        t.x = tf32_rn(v.x); t.y = tf32_rn(v.y);
        t.z = tf32_rn(v.z); t.w = tf32_rn(v.w);
        wdst[i4] = t;
    }

    if (blockIdx.x == 0) {
        for (int i = tid; i < KCODES; i += 256) g_counts[i] = 0;
        if (tid == 0) { g_lossSum = 0.f; g_candCount = 0; }
    }
}

__global__ void vq_rownorm(const float* __restrict__ inp)
{
    const int warp = threadIdx.x >> 5, lane = threadIdx.x & 31;
    const int row = blockIdx.x * 8 + warp;
    const float* xr = inp + (size_t)row * DIM;
    float s = 0.f;
#pragma unroll
    for (int i = 0; i < 8; i++) { float v = xr[lane + i * 32]; s = fmaf(v, v, s); }
#pragma unroll
    for (int o = 16; o > 0; o >>= 1) s += __shfl_xor_sync(0xffffffffu, s, o);
    if (lane == 0) { g_rowNorm[row] = s; g_key[row] = 0xFFFFFFFFFFFFFFFFull; }
}

// ---------------------------------------------------------------------------
extern __shared__ char dynsmem[];

// slice t (0..63): iter = t>>1 (cg = iter>>3, ks = iter&7), half = t&1.
// Covers global cols [(cg*2+half)*128, +128), k slab [ks*32, +32). Slot t&3.
__device__ __forceinline__ void issueB(uint32_t sbB, int t, int tid)
{
    const int iter = t >> 1, h = t & 1;
    const int cg = iter >> 3, ks = iter & 7;
    const int colBlk = cg * 2 + h;
    const uint32_t dbase = sbB + (uint32_t)(t & 3) * (uint32_t)(BSTGF * 4);
#pragma unroll
    for (int j = 0; j < 2; j++) {
        int gi = tid + j * NT;
        int col = gi >> 3, kq = gi & 7;
        uint32_t dst = dbase + (uint32_t)(col * LDBS + kq * 4) * 4u;
        const float* src = g_wtf + ((size_t)(colBlk * 128 + col) * DIM + ks * 32 + kq * 4);
        CP_ASYNC16(dst, src);
    }
    CP_COMMIT();
}

__global__ void __launch_bounds__(NT, 1)
vq_mma(const float* __restrict__ X)
{
    float*    As  = (float*)(dynsmem + SO_A);
    float*    Bs  = (float*)(dynsmem + SO_B);
    float*    CNs = (float*)(dynsmem + SO_CN);
    float*    FBs = (float*)(dynsmem + SO_FB);
    int*      RC  = (int*)(dynsmem + SO_RC);
    float*    LD  = (float*)(dynsmem + SO_LD);
    unsigned* LP  = (unsigned*)(dynsmem + SO_LP);
    int*      s_cnt = (int*)(dynsmem + SO_CNT);

    const int tid = threadIdx.x;
    const int warp = tid >> 5, lane = tid & 31;
    const int wm = warp >> 2, wn = warp & 3;      // 4x4 warp grid
    const int g = lane >> 2, tg = lane & 3;
    const int rowBase = blockIdx.x * BM;
    const uint32_t sbB = smem_u32(dynsmem + SO_B);

    if (tid == 0) *s_cnt = 0;
    if (tid < BM) RC[tid] = 0;

    // prologue: issue slices for iters 0 and 1 (4 half-slices)
    issueB(sbB, 0, tid);
    issueB(sbB, 1, tid);
    issueB(sbB, 2, tid);
    issueB(sbB, 3, tid);

    // A tile: load, tf32-round, NATURAL layout (scalar frag reads are
    // conflict-free: bank = 4g + t + 8*k8)
#pragma unroll
    for (int j = 0; j < 16; j++) {
        int l4 = tid + j * NT;
        int row = l4 >> 6, c4 = l4 & 63;
        float4 v = __ldg((const float4*)(X + (size_t)(rowBase + row) * DIM + c4 * 4));
        float* base = As + row * LDAS + c4 * 4;
        base[0] = tf32_rn(v.x);
        base[1] = tf32_rn(v.y);
        base[2] = tf32_rn(v.z);
        base[3] = tf32_rn(v.w);
    }
#pragma unroll
    for (int j = 0; j < 2; j++) CNs[tid + j * NT] = g_codeNorm[tid + j * NT];

    float xn[4], best[4];
#pragma unroll
    for (int s = 0; s < 4; s++) {
        int rl = wm * 32 + (s >> 1) * 16 + (s & 1) * 8 + g;
        xn[s] = g_rowNorm[rowBase + rl];
        best[s] = 3.4e38f;
    }

    const int hw = wn >> 1;                 // which half-slice this warp reads
    const int colLoc = (wn & 1) * 64;       // col offset within the half

    for (int cg = 0; cg < NGROUPS; cg++) {
        float acc[2][8][4];
#pragma unroll
        for (int mi = 0; mi < 2; mi++)
#pragma unroll
            for (int ni = 0; ni < 8; ni++)
#pragma unroll
                for (int q = 0; q < 4; q++) acc[mi][ni][q] = 0.f;

        for (int ks = 0; ks < KSITER; ks++) {
            const int it = cg * KSITER + ks;
            if (it < NITERS - 2) CP_WAIT(2);
            else                 CP_WAIT(0);
            __syncthreads();                       // slices ready; A ready (it=0)
            const float* Bst = Bs + ((it * 2 + hw) & 3) * BSTGF;

#pragma unroll
            for (int k8 = 0; k8 < 4; k8++) {
                const int ka = ks * 32 + k8 * 8 + tg;
                const int kb = k8 * 8 + tg;
                uint32_t aF[2][4];
#pragma unroll
                for (int mi = 0; mi < 2; mi++) {
                    const float* ap = As + (wm * 32 + mi * 16 + g) * LDAS;
                    aF[mi][0] = __float_as_uint(ap[ka]);
                    aF[mi][1] = __float_as_uint(ap[8 * LDAS + ka]);
                    aF[mi][2] = __float_as_uint(ap[ka + 4]);
                    aF[mi][3] = __float_as_uint(ap[8 * LDAS + ka + 4]);
                }
#pragma unroll
                for (int ni = 0; ni < 8; ni++) {
                    const float* bp = Bst + (colLoc + ni * 8 + g) * LDBS;
                    uint32_t b0 = __float_as_uint(bp[kb]);
                    uint32_t b1 = __float_as_uint(bp[kb + 4]);
                    mma_tf32(acc[0][ni], aF[0], b0, b1);
                    mma_tf32(acc[1][ni], aF[1], b0, b1);
                }
            }
            __syncthreads();                       // all warps done with slots
            if (it + 2 < NITERS) {                 // refill the freed pair
                issueB(sbB, (it + 2) * 2, tid);
                issueB(sbB, (it + 2) * 2 + 1, tid);
            }
        }

        // epilogue: pass A (dists in-place + tighten), pass B (append)
        const int cgBase = cg * BG;
        float cmin[4] = {3.4e38f, 3.4e38f, 3.4e38f, 3.4e38f};
#pragma unroll
        for (int mi = 0; mi < 2; mi++) {
            const int s0 = mi * 2, s1 = mi * 2 + 1;
#pragma unroll
            for (int ni = 0; ni < 8; ni++) {
                int col0 = cgBase + wn * 64 + ni * 8 + tg * 2;
                float cn0 = CNs[col0], cn1 = CNs[col0 + 1];
                float d;
                d = __fadd_rn(__fadd_rn(xn[s0], cn0), -2.0f * acc[mi][ni][0]);
                acc[mi][ni][0] = d; cmin[s0] = fminf(cmin[s0], d);
                d = __fadd_rn(__fadd_rn(xn[s0], cn1), -2.0f * acc[mi][ni][1]);
                acc[mi][ni][1] = d; cmin[s0] = fminf(cmin[s0], d);
                d = __fadd_rn(__fadd_rn(xn[s1], cn0), -2.0f * acc[mi][ni][2]);
                acc[mi][ni][2] = d; cmin[s1] = fminf(cmin[s1], d);
                d = __fadd_rn(__fadd_rn(xn[s1], cn1), -2.0f * acc[mi][ni][3]);
                acc[mi][ni][3] = d; cmin[s1] = fminf(cmin[s1], d);
            }
        }
#pragma unroll
        for (int s = 0; s < 4; s++) {
            cmin[s] = fminf(cmin[s], __shfl_xor_sync(0xffffffffu, cmin[s], 1));
            cmin[s] = fminf(cmin[s], __shfl_xor_sync(0xffffffffu, cmin[s], 2));
            best[s] = fminf(best[s], cmin[s]);
        }
#pragma unroll
        for (int mi = 0; mi < 2; mi++) {
            const int rl0 = wm * 32 + mi * 16 + g;
            const int s0 = mi * 2, s1 = mi * 2 + 1;
#pragma unroll
            for (int ni = 0; ni < 8; ni++) {
                int col0 = cgBase + wn * 64 + ni * 8 + tg * 2;
#pragma unroll
                for (int q = 0; q < 4; q++) {
                    float d = acc[mi][ni][q];
                    int s = (q >> 1) ? s1 : s0;
                    if (d <= best[s] + THR) {
                        int rl = rl0 + (q >> 1) * 8;
                        int col = col0 + (q & 1);
                        int i = atomicAdd(s_cnt, 1);
                        if (i < LCAP) {
                            LD[i] = d;
                            LP[i] = ((unsigned)rl << 10) | (unsigned)col;
                        } else {
                            int gi = atomicAdd(&g_candCount, 1);
                            if (gi < GCAP)
                                g_cand[gi] = ((unsigned)(rowBase + rl) << 10) | (unsigned)col;
                        }
                    }
                }
            }
        }
    }

    // per-row final approx best: 4 sequential merge rounds over wn
    __syncthreads();
    for (int r = 0; r < 4; r++) {
        if (wn == r && tg == 0) {
#pragma unroll
            for (int s = 0; s < 4; s++) {
                int rl = wm * 32 + (s >> 1) * 16 + (s & 1) * 8 + g;
                FBs[rl] = (r == 0) ? best[s] : fminf(FBs[rl], best[s]);
            }
        }
        __syncthreads();
    }

    const int n = min(*s_cnt, LCAP);
    const bool ovf = (*s_cnt > LCAP);
    for (int i = tid; i < n; i += NT) {
        unsigned p = LP[i];
        int rl = p >> 10;
        if (LD[i] <= FBs[rl] + THR) atomicAdd(&RC[rl], 1);
    }
    __syncthreads();
    for (int i = tid; i < n; i += NT) {
        unsigned p = LP[i];
        int rl = p >> 10;
        if (LD[i] <= FBs[rl] + THR) {
            unsigned col = p & 1023u;
            if (!ovf && RC[rl] == 1) {
                g_key[rowBase + rl] = (unsigned long long)col;
            } else {
                int gi = atomicAdd(&g_candCount, 1);
                if (gi < GCAP)
                    g_cand[gi] = ((unsigned)(rowBase + rl) << 10) | col;
            }
        }
    }
}

// ---------------------------------------------------------------------------
__global__ void __launch_bounds__(256)
vq_refine(const float* __restrict__ X, const float* __restrict__ W)
{
    __shared__ float buf[8][512];
    const int warp = threadIdx.x >> 5, lane = threadIdx.x & 31;
    const int wg = blockIdx.x * 8 + warp;
    const int nw = gridDim.x * 8;
    const int count = min(g_candCount, GCAP);
    for (int e = wg; e < count; e += nw) {
        unsigned ent = g_cand[e];
        int row = ent >> 10, col = ent & 1023;
#pragma unroll
        for (int j = 0; j < 8; j++) {
            buf[warp][lane + j * 32]       = __ldg(X + (size_t)row * DIM + lane + j * 32);
            buf[warp][256 + lane + j * 32] = __ldg(W + (size_t)col * DIM + lane + j * 32);
        }
        __syncwarp();
        if (lane == 0) {
            float acc = 0.f;
#pragma unroll 8
            for (int k = 0; k < DIM; k++)
                acc = fmaf(buf[warp][k], buf[warp][256 + k], acc);
            float t = __fadd_rn(g_rowNorm[row], g_codeNorm[col]);
            float d = __fadd_rn(t, -2.0f * acc);
            unsigned long long key =
                (((unsigned long long)__float_as_uint(d)) << 16) | (unsigned)col;
            atomicMin(&g_key[row], key);
        }
        __syncwarp();
    }
}

// ---------------------------------------------------------------------------
__global__ void vq_quant(const float* __restrict__ inp, const float* __restrict__ wt,
                         float* __restrict__ out)
{
    __shared__ float bsum[8];
    const int warp = threadIdx.x >> 5, lane = threadIdx.x & 31;
    const int row = blockIdx.x * 8 + warp;
    const int idx = (int)(g_key[row] & 0xFFFFull);

    const float4* x = (const float4*)(inp + (size_t)row * DIM);
    const float4* w = (const float4*)(wt + (size_t)idx * DIM);
    float4* oi = (float4*)(out + (size_t)row * DIM);
    float4* oq = (float4*)(out + OFF_QUANT + (size_t)row * DIM);
    float4* oe = (float4*)(out + OFF_ENC + (size_t)row * KCODES);

    float s = 0.f;
#pragma unroll
    for (int t = 0; t < 2; t++) {
        int p = lane + t * 32;
        float4 xv = __ldg(x + p);
        float4 wv = __ldg(w + p);
        oi[p] = xv;
        float4 qs;
        qs.x = __fadd_rn(xv.x, __fadd_rn(wv.x, -xv.x));
        qs.y = __fadd_rn(xv.y, __fadd_rn(wv.y, -xv.y));
        qs.z = __fadd_rn(xv.z, __fadd_rn(wv.z, -xv.z));
        qs.w = __fadd_rn(xv.w, __fadd_rn(wv.w, -xv.w));
        oq[p] = qs;
        float dx = wv.x - xv.x, dy = wv.y - xv.y;
        float dz = wv.z - xv.z, dw = wv.w - xv.w;
        s += dx * dx + dy * dy + dz * dz + dw * dw;
    }
#pragma unroll
    for (int t = 0; t < 8; t++) {
        int p = lane + t * 32;
        int base = p * 4;
        float4 v = make_float4(0.f, 0.f, 0.f, 0.f);
        int d = idx - base;
        if (d >= 0 && d < 4) {
            if (d == 0) v.x = 1.f; else if (d == 1) v.y = 1.f;
            else if (d == 2) v.z = 1.f; else v.w = 1.f;
        }
        oe[p] = v;
    }
#pragma unroll
    for (int o = 16; o > 0; o >>= 1) s += __shfl_xor_sync(0xffffffffu, s, o);
    if (lane == 0) { bsum[warp] = s; atomicAdd(&g_counts[idx], 1); }
    __syncthreads();
    if (threadIdx.x == 0) {
        float t = bsum[0] + bsum[1] + bsum[2] + bsum[3]
                + bsum[4] + bsum[5] + bsum[6] + bsum[7];
        atomicAdd(&g_lossSum, t);
    }
}

__global__ void vq_final(float* __restrict__ out)
{
    __shared__ float red[1024];
    int t = threadIdx.x;
    float p = (float)g_counts[t] * (1.0f / (float)N_VEC);
    red[t] = p * logf(p + 1e-10f);
    __syncthreads();
    for (int o = 512; o > 0; o >>= 1) {
        if (t < o) red[t] += red[t + o];
        __syncthreads();
    }
    if (t == 0) {
        float loss = g_lossSum * (1.0f / (float)(N_VEC * DIM));
        out[OFF_QLOSS]     = loss;
        out[OFF_QLOSS + 1] = loss;
        out[OFF_QLOSS + 2] = expf(-red[0]);
    }
}

// ---------------------------------------------------------------------------
extern "C" void kernel_launch(void* const* d_in, const int* in_sizes, int n_in,
                              void* d_out, int out_size)
{
    const float* inp = (const float*)d_in[0];
    const float* wt  = (const float*)d_in[1];
    if (n_in >= 2 && in_sizes[0] == KCODES * DIM && in_sizes[1] == N_VEC * DIM) {
        const float* tmp = inp; inp = wt; wt = tmp;
    }
    float* out = (float*)d_out;

    static bool attrDone = false;
    if (!attrDone) {
        (void)cudaFuncSetAttribute(vq_mma, cudaFuncAttributeMaxDynamicSharedMemorySize,
                                   SM_TOTAL);
        attrDone = true;
    }

    vq_dummy<<<1, 32>>>();
    vq_init<<<KCODES / 8, 256>>>(wt);
    vq_rownorm<<<N_VEC / 8, 256>>>(inp);
    vq_mma<<<N_VEC / BM, NT, SM_TOTAL>>>(inp);
    vq_refine<<<148, 256>>>(inp, wt);
    vq_quant<<<N_VEC / 8, 256>>>(inp, wt, out);
    vq_final<<<1, 1024>>>(out);
}